// round 6
// baseline (speedup 1.0000x reference)
#include <cuda_runtime.h>
#include <cuda_bf16.h>
#include <cstdint>

// ---------------------------------------------------------------------------
// DependencyParsingNetwork: emb-gather + 2-layer BiLSTM (H=50) + pairwise tanh
// R6: chain-trim round. Padded pre buffers -> pointer-only prefetch (no clamp
// ALU on the serial chain), 2-chain dot accumulators (shorter tree),
// z-batched GEMM launches. MUFU.TANH activations, single-shfl handoff kept.
// ---------------------------------------------------------------------------

#define NMAX 8192
#define HH   50
#define PADR 4          // padding rows before/after each direction's pre data

typedef unsigned long long ull;

__device__ float g_x0[NMAX * 352];          // also reused as garbage dump
__device__ float g_pre0[2 * (NMAX + 2 * PADR) * 200];
__device__ float g_pre1[2 * (NMAX + 2 * PADR) * 200];
__device__ float g_h0[NMAX * 100];
__device__ float g_h1[NMAX * 100];
__device__ float g_si[NMAX];
__device__ float g_sj[NMAX];

// ---------------- packed f32x2 / MUFU helpers ------------------------------
__device__ __forceinline__ ull pack2(float x, float y) {
    ull r; asm("mov.b64 %0,{%1,%2};" : "=l"(r) : "f"(x), "f"(y)); return r;
}
__device__ __forceinline__ float2 unpack2(ull v) {
    float2 r; asm("mov.b64 {%0,%1},%2;" : "=f"(r.x), "=f"(r.y) : "l"(v)); return r;
}
__device__ __forceinline__ ull fma2(ull a, ull b, ull c) {
    ull d; asm("fma.rn.f32x2 %0,%1,%2,%3;" : "=l"(d) : "l"(a), "l"(b), "l"(c)); return d;
}
__device__ __forceinline__ ull add2(ull a, ull b) {
    ull d; asm("add.rn.f32x2 %0,%1,%2;" : "=l"(d) : "l"(a), "l"(b)); return d;
}
__device__ __forceinline__ float tanhf_hw(float x) {
    float y; asm("tanh.approx.f32 %0,%1;" : "=f"(y) : "f"(x)); return y;
}

// ---------------- 1) build x0 ----------------------------------------------
__global__ void build_x0_kernel(const int* __restrict__ tok,
                                const float* __restrict__ pos,
                                const float* __restrict__ emb,
                                float* __restrict__ x0, int n) {
    int t = blockIdx.x;
    int tk = tok[t];
    for (int k = threadIdx.x; k < 352; k += blockDim.x) {
        float v;
        if (k < 300)      v = emb[(size_t)tk * 300 + k];
        else if (k < 350) v = pos[t * 50 + (k - 300)];
        else              v = 0.0f;
        x0[(size_t)t * 352 + k] = v;
    }
}

// ---------------- 2) GEMM: C = A*B^T + bias, z-batched fwd/bwd -------------
// prescale: sigmoid rows (i,f,o) get *0.5 (sig(v)=0.5*tanh(v/2)+0.5);
// tanh rows (g: 100..149) stay *1.
__global__ void __launch_bounds__(256)
gemm_bias_kernel(const float* __restrict__ A, int lda,
                 const float* __restrict__ Bf, const float* __restrict__ Bb, int ldb,
                 const float* __restrict__ biasf, const float* __restrict__ biasb,
                 float* __restrict__ Cf, float* __restrict__ Cb, int ldc,
                 int M, int N, int K) {
    const int BM = 64, BN = 64, BK = 16;
    __shared__ __align__(16) float As[BK][BM + 4];
    __shared__ __align__(16) float Bs[BK][BN + 4];
    int tid = threadIdx.x;
    int bm = blockIdx.x * BM, bn = blockIdx.y * BN;
    int tx = tid & 15, ty = tid >> 4;

    const float* B = blockIdx.z ? Bb : Bf;
    const float* bias = blockIdx.z ? biasb : biasf;
    float* C = blockIdx.z ? Cb : Cf;

    float acc[4][4];
#pragma unroll
    for (int i = 0; i < 4; i++)
#pragma unroll
        for (int j = 0; j < 4; j++) acc[i][j] = 0.0f;

    for (int k0 = 0; k0 < K; k0 += BK) {
#pragma unroll
        for (int i = 0; i < 4; i++) {
            int idx = tid + i * 256;
            int kk = idx & 15, m = idx >> 4;
            int gm = bm + m, gk = k0 + kk;
            float v = 0.0f;
            if (gm < M && gk < K) v = A[(size_t)gm * lda + gk];
            As[kk][m] = v;
        }
#pragma unroll
        for (int i = 0; i < 4; i++) {
            int idx = tid + i * 256;
            int kk = idx & 15, nn = idx >> 4;
            int gn = bn + nn, gk = k0 + kk;
            float v = 0.0f;
            if (gn < N && gk < K) v = B[(size_t)gn * ldb + gk];
            Bs[kk][nn] = v;
        }
        __syncthreads();
#pragma unroll
        for (int kk = 0; kk < BK; kk++) {
            float4 a4 = *reinterpret_cast<const float4*>(&As[kk][ty * 4]);
            float4 b4 = *reinterpret_cast<const float4*>(&Bs[kk][tx * 4]);
            float a[4] = {a4.x, a4.y, a4.z, a4.w};
            float b[4] = {b4.x, b4.y, b4.z, b4.w};
#pragma unroll
            for (int i = 0; i < 4; i++)
#pragma unroll
                for (int j = 0; j < 4; j++) acc[i][j] += a[i] * b[j];
        }
        __syncthreads();
    }
#pragma unroll
    for (int i = 0; i < 4; i++) {
        int gm = bm + ty * 4 + i;
        if (gm >= M) continue;
#pragma unroll
        for (int j = 0; j < 4; j++) {
            int gn = bn + tx * 4 + j;
            if (gn < N) {
                float sc = (gn >= 100 && gn < 150) ? 1.0f : 0.5f;
                C[(size_t)gm * ldc + gn] = (acc[i][j] + bias[gn]) * sc;
            }
        }
    }
}

// ---------------- 3/5) recurrence: branch-free, pointer-only prefetch ------
// thread t: j=t>>1, p=t&1. p0 owns rows i(j), g(100+j); p1 owns f(50+j),
// o(150+j). Pre-acts arrive scaled 0.5 (sigmoid rows) / 1.0 (g rows).
// sigmoid = 0.5*tanh(u)+0.5; tanh = tanh(u). p0 ships i*g via one xor-1
// shfl; p1 keeps c, computes h, stores. pre has PADR-row slack both sides
// so the 3-deep prefetch never needs clamping.
__global__ void __launch_bounds__(128, 1)
lstm_layer_kernel(const float* __restrict__ pre,   // padded, prescaled
                  const float* __restrict__ whh_f, // [200][50]
                  const float* __restrict__ whh_b,
                  float* __restrict__ hout,        // [n][100]
                  float* __restrict__ dump,        // garbage sink
                  int n) {
    const int dir = blockIdx.x;
    const float* __restrict__ preD =
        pre + (size_t)dir * (NMAX + 2 * PADR) * 200 + (size_t)PADR * 200;
    const float* __restrict__ whh = dir ? whh_b : whh_f;

    const int t = threadIdx.x;
    const int j = t >> 1, p = t & 1;
    const bool wr = (p == 1) && (j < HH);       // p1 writes h
    const int rA = min(p * HH + j, 199);        // i (p0) / f (p1)
    const int rBc = min(p * HH + j + 100, 199); // g (p0) / o (p1)

    const float sclA = 0.5f;                         // i,f sigmoid
    const float sclB = (p == 0) ? 1.0f : 0.5f;       // g tanh / o sigmoid
    const float mB   = (p == 0) ? 1.0f : 0.5f;
    const float cstB = (p == 0) ? 0.0f : 0.5f;

    // persistent prescaled weight rows: 2 x 25 packed pairs
    ull wA[25], wB[25];
#pragma unroll
    for (int k = 0; k < 25; k++) {
        wA[k] = pack2(whh[rA * HH + 2 * k] * sclA, whh[rA * HH + 2 * k + 1] * sclA);
        wB[k] = pack2(whh[rBc * HH + 2 * k] * sclB, whh[rBc * HH + 2 * k + 1] * sclB);
    }

    __shared__ __align__(16) float hsh[2][128];   // [0..49] real, [64..127] scratch
    if (t < 64) { hsh[0][t] = 0.0f; hsh[1][t] = 0.0f; }
    float c = 0.0f;

    // precomputed store targets -> zero branches in loop body
    float* st0 = &hsh[1][wr ? j : (64 + j)];
    float* st1 = &hsh[0][wr ? j : (64 + j)];
    float* phW;
    long long hOffW;
    if (wr) {
        phW = hout + (size_t)(dir ? (n - 1) : 0) * 100 + dir * HH + j;
        hOffW = dir ? -100 : 100;
    } else {
        phW = dump + dir * 256 + t;
        hOffW = 0;
    }

    // 3-deep prefetch: pure pointer increments into padded buffer
    const long long stepOff = dir ? -200 : 200;
    const float* pf = preD + (size_t)(dir ? (n - 1) : 0) * 200;
    float a0 = pf[rA], b0 = pf[rBc]; pf += stepOff;
    float a1 = pf[rA], b1 = pf[rBc]; pf += stepOff;
    float a2 = pf[rA], b2 = pf[rBc]; pf += stepOff;
    __syncthreads();

    auto step_fn = [&](const float* hb, float* sts, float pa, float pb) {
        ull hp[25];
#pragma unroll
        for (int i2 = 0; i2 < 12; i2++) {
            ulonglong2 hv = *reinterpret_cast<const ulonglong2*>(hb + 4 * i2);
            hp[2 * i2] = hv.x; hp[2 * i2 + 1] = hv.y;
        }
        hp[24] = *reinterpret_cast<const ull*>(hb + 48);

        // 2 accumulator chains per dot (dep 13x4=52 < issue block)
        ull aA0 = pack2(pa, 0.0f), aA1 = pack2(0.0f, 0.0f);
        ull aB0 = pack2(pb, 0.0f), aB1 = pack2(0.0f, 0.0f);
#pragma unroll
        for (int k = 0; k < 24; k += 2) {
            aA0 = fma2(wA[k], hp[k], aA0);
            aA1 = fma2(wA[k + 1], hp[k + 1], aA1);
            aB0 = fma2(wB[k], hp[k], aB0);
            aB1 = fma2(wB[k + 1], hp[k + 1], aB1);
        }
        aA0 = fma2(wA[24], hp[24], aA0);
        aB0 = fma2(wB[24], hp[24], aB0);
        float2 fA = unpack2(add2(aA0, aA1));
        float2 fB = unpack2(add2(aB0, aB1));
        float vA = fA.x + fA.y;
        float vB = fB.x + fB.y;

        // activations: yA = sig (p0:i, p1:f); yB = p0: tanh(g), p1: sig(o)
        float yA = fmaf(0.5f, tanhf_hw(vA), 0.5f);
        float yB = fmaf(mB, tanhf_hw(vB), cstB);

        float mg = yA * yB;                               // i*g on p0
        float mgx = __shfl_xor_sync(0xFFFFFFFFu, mg, 1);  // p1 receives i*g
        c = fmaf(yA, c, mgx);                             // p1: f*c + i*g
        float h = yB * tanhf_hw(c);                       // p1: o * tanh(c)
        *sts = h;
        *phW = h;
        phW += hOffW;
    };

    int s = 0;
#pragma unroll 1
    for (; s + 2 <= n; s += 2) {
        float na = pf[rA], nb = pf[rBc]; pf += stepOff;   // prefetch s+3
        step_fn(hsh[0], st0, a0, b0);                     // step s
        a0 = a1; b0 = b1; a1 = a2; b1 = b2; a2 = na; b2 = nb;
        __syncthreads();

        na = pf[rA]; nb = pf[rBc]; pf += stepOff;         // prefetch s+4
        step_fn(hsh[1], st1, a0, b0);                     // step s+1
        a0 = a1; b0 = b1; a1 = a2; b1 = b2; a2 = na; b2 = nb;
        __syncthreads();
    }
    if (s < n) {
        step_fn(hsh[0], st0, a0, b0);
        __syncthreads();
    }
}

// ---------------- 6a) per-token endpoint scores ----------------------------
__global__ void score_vec_kernel(const float* __restrict__ h1,
                                 const float* __restrict__ mlpw,
                                 float* __restrict__ si, float* __restrict__ sj,
                                 int n) {
    int t = blockIdx.x * blockDim.x + threadIdx.x;
    if (t >= n) return;
    const float* x = h1 + (size_t)t * 100;
    float a = 0.0f, b = 0.0f;
#pragma unroll 4
    for (int k = 0; k < 100; k++) {
        float xv = x[k];
        a += xv * __ldg(mlpw + k);
        b += xv * __ldg(mlpw + 100 + k);
    }
    si[t] = a;
    sj[t] = b;
}

// ---------------- 6b) pairwise epilogue ------------------------------------
__global__ void __launch_bounds__(256)
epilogue_kernel(const float* __restrict__ si, const float* __restrict__ sj,
                const float* __restrict__ mb, float* __restrict__ out, int n) {
    int i = blockIdx.y;
    int j4 = blockIdx.x * blockDim.x + threadIdx.x;
    int j0 = j4 * 4;
    if (j0 >= n) return;
    float base = si[i] + mb[0];
    float4 r;
    r.x = (j0 + 0 > i) ? tanhf_hw(base + sj[j0 + 0]) : 0.0f;
    r.y = (j0 + 1 > i) ? tanhf_hw(base + sj[j0 + 1]) : 0.0f;
    r.z = (j0 + 2 > i) ? tanhf_hw(base + sj[j0 + 2]) : 0.0f;
    r.w = (j0 + 3 > i) ? tanhf_hw(base + sj[j0 + 3]) : 0.0f;
    *reinterpret_cast<float4*>(out + (size_t)i * n + j0) = r;
}

// ---------------------------------------------------------------------------
extern "C" void kernel_launch(void* const* d_in, const int* in_sizes, int n_in,
                              void* d_out, int out_size) {
    const int*   tok   = (const int*)d_in[0];
    const float* pos   = (const float*)d_in[1];
    const float* emb   = (const float*)d_in[2];
    const float* wih0f = (const float*)d_in[3];
    const float* whh0f = (const float*)d_in[4];
    const float* b0f   = (const float*)d_in[5];
    const float* wih0b = (const float*)d_in[6];
    const float* whh0b = (const float*)d_in[7];
    const float* b0b   = (const float*)d_in[8];
    const float* wih1f = (const float*)d_in[9];
    const float* whh1f = (const float*)d_in[10];
    const float* b1f   = (const float*)d_in[11];
    const float* wih1b = (const float*)d_in[12];
    const float* whh1b = (const float*)d_in[13];
    const float* b1b   = (const float*)d_in[14];
    const float* mlpw  = (const float*)d_in[15];
    const float* mlpb  = (const float*)d_in[16];

    int n = in_sizes[0];
    if (n > NMAX) n = NMAX;

    float *x0, *pre0, *pre1, *h0, *h1, *si, *sj;
    cudaGetSymbolAddress((void**)&x0,   g_x0);
    cudaGetSymbolAddress((void**)&pre0, g_pre0);
    cudaGetSymbolAddress((void**)&pre1, g_pre1);
    cudaGetSymbolAddress((void**)&h0,   g_h0);
    cudaGetSymbolAddress((void**)&h1,   g_h1);
    cudaGetSymbolAddress((void**)&si,   g_si);
    cudaGetSymbolAddress((void**)&sj,   g_sj);

    const size_t dirStride = (size_t)(NMAX + 2 * PADR) * 200;
    float* pre0f = pre0 + (size_t)PADR * 200;
    float* pre0b = pre0f + dirStride;
    float* pre1f = pre1 + (size_t)PADR * 200;
    float* pre1b = pre1f + dirStride;

    build_x0_kernel<<<n, 128>>>(tok, pos, emb, x0, n);

    {
        dim3 grid((n + 63) / 64, (200 + 63) / 64, 2);
        gemm_bias_kernel<<<grid, 256>>>(x0, 352, wih0f, wih0b, 350,
                                        b0f, b0b, pre0f, pre0b, 200,
                                        n, 200, 350);
    }

    lstm_layer_kernel<<<2, 128>>>(pre0, whh0f, whh0b, h0, x0, n);

    {
        dim3 grid((n + 63) / 64, (200 + 63) / 64, 2);
        gemm_bias_kernel<<<grid, 256>>>(h0, 100, wih1f, wih1b, 100,
                                        b1f, b1b, pre1f, pre1b, 200,
                                        n, 200, 100);
    }

    lstm_layer_kernel<<<2, 128>>>(pre1, whh1f, whh1b, h1, x0, n);

    score_vec_kernel<<<(n + 255) / 256, 256>>>(h1, mlpw, si, sj, n);
    {
        dim3 grid((n / 4 + 255) / 256, n);
        epilogue_kernel<<<grid, 256>>>(si, sj, mlpb, (float*)d_out, n);
    }
}

// round 9
// speedup vs baseline: 1.1642x; 1.1642x over previous
#include <cuda_runtime.h>
#include <cuda_bf16.h>
#include <cstdint>

// ---------------------------------------------------------------------------
// DependencyParsingNetwork: emb-gather + 2-layer BiLSTM (H=50) + pairwise tanh
// R7: revert to 4-chain dot (R6's 2-chain lengthened the dep chain), keep
// padded pointer-only prefetch + z-batched GEMM, add 2-shfl tail (c on p0)
// and 4x unrolled recurrence loop.
// ---------------------------------------------------------------------------

#define NMAX 8192
#define HH   50
#define PADR 8          // padding rows before/after each direction's pre data

typedef unsigned long long ull;

__device__ float g_x0[NMAX * 352];          // also reused as garbage dump
__device__ float g_pre0[2 * (NMAX + 2 * PADR) * 200];
__device__ float g_pre1[2 * (NMAX + 2 * PADR) * 200];
__device__ float g_h0[NMAX * 100];
__device__ float g_h1[NMAX * 100];
__device__ float g_si[NMAX];
__device__ float g_sj[NMAX];

// ---------------- packed f32x2 / MUFU helpers ------------------------------
__device__ __forceinline__ ull pack2(float x, float y) {
    ull r; asm("mov.b64 %0,{%1,%2};" : "=l"(r) : "f"(x), "f"(y)); return r;
}
__device__ __forceinline__ float2 unpack2(ull v) {
    float2 r; asm("mov.b64 {%0,%1},%2;" : "=f"(r.x), "=f"(r.y) : "l"(v)); return r;
}
__device__ __forceinline__ ull fma2(ull a, ull b, ull c) {
    ull d; asm("fma.rn.f32x2 %0,%1,%2,%3;" : "=l"(d) : "l"(a), "l"(b), "l"(c)); return d;
}
__device__ __forceinline__ ull add2(ull a, ull b) {
    ull d; asm("add.rn.f32x2 %0,%1,%2;" : "=l"(d) : "l"(a), "l"(b)); return d;
}
__device__ __forceinline__ float tanhf_hw(float x) {
    float y; asm("tanh.approx.f32 %0,%1;" : "=f"(y) : "f"(x)); return y;
}

// ---------------- 1) build x0 ----------------------------------------------
__global__ void build_x0_kernel(const int* __restrict__ tok,
                                const float* __restrict__ pos,
                                const float* __restrict__ emb,
                                float* __restrict__ x0, int n) {
    int t = blockIdx.x;
    int tk = tok[t];
    for (int k = threadIdx.x; k < 352; k += blockDim.x) {
        float v;
        if (k < 300)      v = emb[(size_t)tk * 300 + k];
        else if (k < 350) v = pos[t * 50 + (k - 300)];
        else              v = 0.0f;
        x0[(size_t)t * 352 + k] = v;
    }
}

// ---------------- 2) GEMM: C = A*B^T + bias, z-batched fwd/bwd -------------
// prescale: sigmoid rows (i,f,o) get *0.5 (sig(v)=0.5*tanh(v/2)+0.5);
// tanh rows (g: 100..149) stay *1.
__global__ void __launch_bounds__(256)
gemm_bias_kernel(const float* __restrict__ A, int lda,
                 const float* __restrict__ Bf, const float* __restrict__ Bb, int ldb,
                 const float* __restrict__ biasf, const float* __restrict__ biasb,
                 float* __restrict__ Cf, float* __restrict__ Cb, int ldc,
                 int M, int N, int K) {
    const int BM = 64, BN = 64, BK = 16;
    __shared__ __align__(16) float As[BK][BM + 4];
    __shared__ __align__(16) float Bs[BK][BN + 4];
    int tid = threadIdx.x;
    int bm = blockIdx.x * BM, bn = blockIdx.y * BN;
    int tx = tid & 15, ty = tid >> 4;

    const float* B = blockIdx.z ? Bb : Bf;
    const float* bias = blockIdx.z ? biasb : biasf;
    float* C = blockIdx.z ? Cb : Cf;

    float acc[4][4];
#pragma unroll
    for (int i = 0; i < 4; i++)
#pragma unroll
        for (int j = 0; j < 4; j++) acc[i][j] = 0.0f;

    for (int k0 = 0; k0 < K; k0 += BK) {
#pragma unroll
        for (int i = 0; i < 4; i++) {
            int idx = tid + i * 256;
            int kk = idx & 15, m = idx >> 4;
            int gm = bm + m, gk = k0 + kk;
            float v = 0.0f;
            if (gm < M && gk < K) v = A[(size_t)gm * lda + gk];
            As[kk][m] = v;
        }
#pragma unroll
        for (int i = 0; i < 4; i++) {
            int idx = tid + i * 256;
            int kk = idx & 15, nn = idx >> 4;
            int gn = bn + nn, gk = k0 + kk;
            float v = 0.0f;
            if (gn < N && gk < K) v = B[(size_t)gn * ldb + gk];
            Bs[kk][nn] = v;
        }
        __syncthreads();
#pragma unroll
        for (int kk = 0; kk < BK; kk++) {
            float4 a4 = *reinterpret_cast<const float4*>(&As[kk][ty * 4]);
            float4 b4 = *reinterpret_cast<const float4*>(&Bs[kk][tx * 4]);
            float a[4] = {a4.x, a4.y, a4.z, a4.w};
            float b[4] = {b4.x, b4.y, b4.z, b4.w};
#pragma unroll
            for (int i = 0; i < 4; i++)
#pragma unroll
                for (int j = 0; j < 4; j++) acc[i][j] += a[i] * b[j];
        }
        __syncthreads();
    }
#pragma unroll
    for (int i = 0; i < 4; i++) {
        int gm = bm + ty * 4 + i;
        if (gm >= M) continue;
#pragma unroll
        for (int j = 0; j < 4; j++) {
            int gn = bn + tx * 4 + j;
            if (gn < N) {
                float sc = (gn >= 100 && gn < 150) ? 1.0f : 0.5f;
                C[(size_t)gm * ldc + gn] = (acc[i][j] + bias[gn]) * sc;
            }
        }
    }
}

// ---------------- 3/5) recurrence ------------------------------------------
// thread t: j=t>>1, p=t&1. p0 owns rows i(j), g(100+j); p1 owns f(50+j),
// o(150+j). Pre-acts arrive scaled 0.5 (sigmoid rows) / 1.0 (g rows).
// sigmoid = 0.5*tanh(u)+0.5; tanh = tanh(u). p1 ships sig(f), sig(o) via two
// independent xor-1 shfls (latencies overlap); p0 owns c, computes h, stores.
__global__ void __launch_bounds__(128, 1)
lstm_layer_kernel(const float* __restrict__ pre,   // padded, prescaled
                  const float* __restrict__ whh_f, // [200][50]
                  const float* __restrict__ whh_b,
                  float* __restrict__ hout,        // [n][100]
                  float* __restrict__ dump,        // garbage sink
                  int n) {
    const int dir = blockIdx.x;
    const float* __restrict__ preD =
        pre + (size_t)dir * (NMAX + 2 * PADR) * 200 + (size_t)PADR * 200;
    const float* __restrict__ whh = dir ? whh_b : whh_f;

    const int t = threadIdx.x;
    const int j = t >> 1, p = t & 1;
    const bool wr = (p == 0) && (j < HH);       // p0 writes h
    const int rA = min(p * HH + j, 199);        // i (p0) / f (p1)
    const int rBc = min(p * HH + j + 100, 199); // g (p0) / o (p1)

    const float sclA = 0.5f;                         // i,f sigmoid
    const float sclB = (p == 0) ? 1.0f : 0.5f;       // g tanh / o sigmoid
    const float mB   = (p == 0) ? 1.0f : 0.5f;
    const float cstB = (p == 0) ? 0.0f : 0.5f;

    // persistent prescaled weight rows: 2 x 25 packed pairs
    ull wA[25], wB[25];
#pragma unroll
    for (int k = 0; k < 25; k++) {
        wA[k] = pack2(whh[rA * HH + 2 * k] * sclA, whh[rA * HH + 2 * k + 1] * sclA);
        wB[k] = pack2(whh[rBc * HH + 2 * k] * sclB, whh[rBc * HH + 2 * k + 1] * sclB);
    }

    __shared__ __align__(16) float hsh[2][128];   // [0..49] real, [64..127] scratch
    if (t < 64) { hsh[0][t] = 0.0f; hsh[1][t] = 0.0f; }
    float c = 0.0f;

    // precomputed store targets -> zero branches in loop body
    float* st0 = &hsh[1][wr ? j : (64 + j)];
    float* st1 = &hsh[0][wr ? j : (64 + j)];
    float* phW;
    long long hOffW;
    if (wr) {
        phW = hout + (size_t)(dir ? (n - 1) : 0) * 100 + dir * HH + j;
        hOffW = dir ? -100 : 100;
    } else {
        phW = dump + dir * 256 + t;
        hOffW = 0;
    }

    // 4-deep prefetch: pure pointer increments into padded buffer
    const long long stepOff = dir ? -200 : 200;
    const float* pf = preD + (size_t)(dir ? (n - 1) : 0) * 200;
    float a0 = pf[rA], b0 = pf[rBc]; pf += stepOff;
    float a1 = pf[rA], b1 = pf[rBc]; pf += stepOff;
    float a2 = pf[rA], b2 = pf[rBc]; pf += stepOff;
    float a3 = pf[rA], b3 = pf[rBc]; pf += stepOff;
    __syncthreads();

    auto step_fn = [&](const float* hb, float* sts, float pa, float pb) {
        ull hp[25];
#pragma unroll
        for (int i2 = 0; i2 < 12; i2++) {
            ulonglong2 hv = *reinterpret_cast<const ulonglong2*>(hb + 4 * i2);
            hp[2 * i2] = hv.x; hp[2 * i2 + 1] = hv.y;
        }
        hp[24] = *reinterpret_cast<const ull*>(hb + 48);

        // 4 accumulator chains per dot (chain depth 7)
        ull aA[4], aB[4];
        aA[0] = pack2(pa, 0.0f); aB[0] = pack2(pb, 0.0f);
        aA[1] = pack2(0.0f, 0.0f); aA[2] = aA[1]; aA[3] = aA[1];
        aB[1] = aA[1]; aB[2] = aA[1]; aB[3] = aA[1];
#pragma unroll
        for (int k = 0; k < 25; k++) {
            aA[k & 3] = fma2(wA[k], hp[k], aA[k & 3]);
            aB[k & 3] = fma2(wB[k], hp[k], aB[k & 3]);
        }
        float2 fA = unpack2(add2(add2(aA[0], aA[1]), add2(aA[2], aA[3])));
        float2 fB = unpack2(add2(add2(aB[0], aB[1]), add2(aB[2], aB[3])));
        float vA = fA.x + fA.y;
        float vB = fB.x + fB.y;

        // activations: yA = sig (p0:i, p1:f); yB = p0: tanh(g), p1: sig(o)
        float yA = fmaf(0.5f, tanhf_hw(vA), 0.5f);
        float yB = fmaf(mB, tanhf_hw(vB), cstB);

        // two independent shfls: p0 receives sig(f), sig(o) from p1
        float fR = __shfl_xor_sync(0xFFFFFFFFu, yA, 1);
        float oR = __shfl_xor_sync(0xFFFFFFFFu, yB, 1);

        c = fmaf(fR, c, yA * yB);           // p0: f*c + i*g (mul overlaps shfl)
        float h = oR * tanhf_hw(c);         // p0: o * tanh(c)
        *sts = h;
        *phW = h;
        phW += hOffW;
    };

    int s = 0;
#pragma unroll 1
    for (; s + 4 <= n; s += 4) {
        float na0 = pf[rA], nb0 = pf[rBc]; pf += stepOff;   // prefetch s+4
        step_fn(hsh[0], st0, a0, b0);                       // step s
        __syncthreads();
        float na1 = pf[rA], nb1 = pf[rBc]; pf += stepOff;   // prefetch s+5
        step_fn(hsh[1], st1, a1, b1);                       // step s+1
        __syncthreads();
        float na2 = pf[rA], nb2 = pf[rBc]; pf += stepOff;   // prefetch s+6
        step_fn(hsh[0], st0, a2, b2);                       // step s+2
        __syncthreads();
        float na3 = pf[rA], nb3 = pf[rBc]; pf += stepOff;   // prefetch s+7
        step_fn(hsh[1], st1, a3, b3);                       // step s+3
        __syncthreads();
        a0 = na0; b0 = nb0; a1 = na1; b1 = nb1;
        a2 = na2; b2 = nb2; a3 = na3; b3 = nb3;
    }
    // remainder (<=3 steps); parity is back at buffer 0 after the 4x loop
    int r = n - s;
    if (r >= 1) { step_fn(hsh[0], st0, a0, b0); __syncthreads(); }
    if (r >= 2) { step_fn(hsh[1], st1, a1, b1); __syncthreads(); }
    if (r >= 3) { step_fn(hsh[0], st0, a2, b2); __syncthreads(); }
}

// ---------------- 6a) per-token endpoint scores ----------------------------
__global__ void score_vec_kernel(const float* __restrict__ h1,
                                 const float* __restrict__ mlpw,
                                 float* __restrict__ si, float* __restrict__ sj,
                                 int n) {
    int t = blockIdx.x * blockDim.x + threadIdx.x;
    if (t >= n) return;
    const float* x = h1 + (size_t)t * 100;
    float a = 0.0f, b = 0.0f;
#pragma unroll 4
    for (int k = 0; k < 100; k++) {
        float xv = x[k];
        a += xv * __ldg(mlpw + k);
        b += xv * __ldg(mlpw + 100 + k);
    }
    si[t] = a;
    sj[t] = b;
}

// ---------------- 6b) pairwise epilogue ------------------------------------
__global__ void __launch_bounds__(256)
epilogue_kernel(const float* __restrict__ si, const float* __restrict__ sj,
                const float* __restrict__ mb, float* __restrict__ out, int n) {
    int i = blockIdx.y;
    int j4 = blockIdx.x * blockDim.x + threadIdx.x;
    int j0 = j4 * 4;
    if (j0 >= n) return;
    float base = si[i] + mb[0];
    float4 r;
    r.x = (j0 + 0 > i) ? tanhf_hw(base + sj[j0 + 0]) : 0.0f;
    r.y = (j0 + 1 > i) ? tanhf_hw(base + sj[j0 + 1]) : 0.0f;
    r.z = (j0 + 2 > i) ? tanhf_hw(base + sj[j0 + 2]) : 0.0f;
    r.w = (j0 + 3 > i) ? tanhf_hw(base + sj[j0 + 3]) : 0.0f;
    *reinterpret_cast<float4*>(out + (size_t)i * n + j0) = r;
}

// ---------------------------------------------------------------------------
extern "C" void kernel_launch(void* const* d_in, const int* in_sizes, int n_in,
                              void* d_out, int out_size) {
    const int*   tok   = (const int*)d_in[0];
    const float* pos   = (const float*)d_in[1];
    const float* emb   = (const float*)d_in[2];
    const float* wih0f = (const float*)d_in[3];
    const float* whh0f = (const float*)d_in[4];
    const float* b0f   = (const float*)d_in[5];
    const float* wih0b = (const float*)d_in[6];
    const float* whh0b = (const float*)d_in[7];
    const float* b0b   = (const float*)d_in[8];
    const float* wih1f = (const float*)d_in[9];
    const float* whh1f = (const float*)d_in[10];
    const float* b1f   = (const float*)d_in[11];
    const float* wih1b = (const float*)d_in[12];
    const float* whh1b = (const float*)d_in[13];
    const float* b1b   = (const float*)d_in[14];
    const float* mlpw  = (const float*)d_in[15];
    const float* mlpb  = (const float*)d_in[16];

    int n = in_sizes[0];
    if (n > NMAX) n = NMAX;

    float *x0, *pre0, *pre1, *h0, *h1, *si, *sj;
    cudaGetSymbolAddress((void**)&x0,   g_x0);
    cudaGetSymbolAddress((void**)&pre0, g_pre0);
    cudaGetSymbolAddress((void**)&pre1, g_pre1);
    cudaGetSymbolAddress((void**)&h0,   g_h0);
    cudaGetSymbolAddress((void**)&h1,   g_h1);
    cudaGetSymbolAddress((void**)&si,   g_si);
    cudaGetSymbolAddress((void**)&sj,   g_sj);

    const size_t dirStride = (size_t)(NMAX + 2 * PADR) * 200;
    float* pre0f = pre0 + (size_t)PADR * 200;
    float* pre0b = pre0f + dirStride;
    float* pre1f = pre1 + (size_t)PADR * 200;
    float* pre1b = pre1f + dirStride;

    build_x0_kernel<<<n, 128>>>(tok, pos, emb, x0, n);

    {
        dim3 grid((n + 63) / 64, (200 + 63) / 64, 2);
        gemm_bias_kernel<<<grid, 256>>>(x0, 352, wih0f, wih0b, 350,
                                        b0f, b0b, pre0f, pre0b, 200,
                                        n, 200, 350);
    }

    lstm_layer_kernel<<<2, 128>>>(pre0, whh0f, whh0b, h0, x0, n);

    {
        dim3 grid((n + 63) / 64, (200 + 63) / 64, 2);
        gemm_bias_kernel<<<grid, 256>>>(h0, 100, wih1f, wih1b, 100,
                                        b1f, b1b, pre1f, pre1b, 200,
                                        n, 200, 100);
    }

    lstm_layer_kernel<<<2, 128>>>(pre1, whh1f, whh1b, h1, x0, n);

    score_vec_kernel<<<(n + 255) / 256, 256>>>(h1, mlpw, si, sj, n);
    {
        dim3 grid((n / 4 + 255) / 256, n);
        epilogue_kernel<<<grid, 256>>>(si, sj, mlpb, (float*)d_out, n);
    }
}